// round 11
// baseline (speedup 1.0000x reference)
#include <cuda_runtime.h>
#include <cuda_fp16.h>
#include <math.h>
#include <stdint.h>

#define CCH   128
#define HIMG  56
#define WIMG  56
#define NIMG  32
#define EPSBN 1e-5f
#define QLEV  255.0f
#define WMAXQ 127.0f

#define NPIX ((size_t)NIMG * CCH * HIMG * WIMG)

// ---------------- device scratch ----------------
__device__ unsigned short g_xhi[NPIX],  g_xlo[NPIX];
__device__ unsigned short g_a1hi[NPIX], g_a1lo[NPIX];
#define WELEMS (8 * 9 * 128 * 16)
__device__ unsigned short g_w1i[WELEMS], g_w2i[WELEMS];
__device__ float g_ws1[CCH], g_ws2[CCH];
__device__ float g_bns1[CCH], g_bnb1[CCH], g_a1p[CCH], g_s1[CCH], g_r1[CCH];
__device__ float g_bns2[CCH], g_bnb2[CCH], g_a2p[CCH], g_s2[CCH], g_r2[CCH];
__device__ float g_a3p[CCH], g_s3[CCH], g_r3[CCH];

// ---------------- PTX helpers ----------------
__device__ __forceinline__ uint32_t smem_u32(const void* p) {
    uint32_t a;
    asm("{ .reg .u64 t; cvta.to.shared.u64 t, %1; cvt.u32.u64 %0, t; }" : "=r"(a) : "l"(p));
    return a;
}

__device__ __forceinline__ void cp16(uint32_t dst, const void* src, int sz) {
    asm volatile("cp.async.cg.shared.global [%0], [%1], 16, %2;"
                 :: "r"(dst), "l"(__cvta_generic_to_global(src)), "r"(sz) : "memory");
}
__device__ __forceinline__ void cp_commit() {
    asm volatile("cp.async.commit_group;" ::: "memory");
}
template <int N> __device__ __forceinline__ void cp_wait() {
    asm volatile("cp.async.wait_group %0;" :: "n"(N) : "memory");
}

__device__ __forceinline__ void ldsm4(uint32_t r[4], uint32_t addr) {
    asm volatile("ldmatrix.sync.aligned.m8n8.x4.shared.b16 {%0,%1,%2,%3}, [%4];"
                 : "=r"(r[0]), "=r"(r[1]), "=r"(r[2]), "=r"(r[3]) : "r"(addr));
}

__device__ __forceinline__ void mma16816(float d[4], const uint32_t a[4],
                                         uint32_t b0, uint32_t b1) {
    asm volatile("mma.sync.aligned.m16n8k16.row.col.f32.f16.f16.f32 "
                 "{%0,%1,%2,%3}, {%4,%5,%6,%7}, {%8,%9}, {%0,%1,%2,%3};"
                 : "+f"(d[0]), "+f"(d[1]), "+f"(d[2]), "+f"(d[3])
                 : "r"(a[0]), "r"(a[1]), "r"(a[2]), "r"(a[3]), "r"(b0), "r"(b1));
}

// exact exponent shift: x * 2^-11 on packed half2 (k integer => stays normal)
__device__ __forceinline__ uint32_t hscale11(uint32_t b) {
    const __half2 s = __floats2half2_rn(4.8828125e-4f, 4.8828125e-4f);
    __half2 v = *reinterpret_cast<__half2*>(&b);
    v = __hmul2(v, s);
    return *reinterpret_cast<uint32_t*>(&v);
}

// ---------------- prep kernels ----------------
__global__ void presplit_x(const float* __restrict__ x) {
    const size_t nsite = (size_t)NIMG * 8 * HIMG * WIMG;
    size_t i = (size_t)blockIdx.x * blockDim.x + threadIdx.x;
    if (i >= nsite) return;
    int w  = (int)(i % 56);
    int h  = (int)((i / 56) % 56);
    int ck = (int)((i / 3136) % 8);
    int n  = (int)(i / 25088);
    unsigned short hi[16], lo[16];
#pragma unroll
    for (int j = 0; j < 16; j++) {
        float v = x[((size_t)(n * 128 + ck * 16 + j)) * 3136 + h * 56 + w];
        __half hh = __float2half_rn(v);
        __half ll = __float2half_rn((v - __half2float(hh)) * 2048.0f);
        hi[j] = __half_as_ushort(hh);
        lo[j] = __half_as_ushort(ll);
    }
    uint4* dh = (uint4*)(g_xhi + i * 16);
    uint4* dl = (uint4*)(g_xlo + i * 16);
    dh[0] = ((uint4*)hi)[0]; dh[1] = ((uint4*)hi)[1];
    dl[0] = ((uint4*)lo)[0]; dl[1] = ((uint4*)lo)[1];
}

__global__ void prep_weights(const float* __restrict__ w1, const float* __restrict__ w2) {
    const int o = blockIdx.x;
    const float* w = (blockIdx.y == 0) ? w1 : w2;
    unsigned short* di = (blockIdx.y == 0) ? g_w1i : g_w2i;
    float* ws          = (blockIdx.y == 0) ? g_ws1 : g_ws2;
    const float* wo = w + (size_t)o * CCH * 9;

    float m = 0.f;
    for (int i = threadIdx.x; i < CCH * 9; i += blockDim.x)
        m = fmaxf(m, fabsf(wo[i]));
    __shared__ float red[256];
    red[threadIdx.x] = m;
    __syncthreads();
    for (int s = 128; s > 0; s >>= 1) {
        if (threadIdx.x < s) red[threadIdx.x] = fmaxf(red[threadIdx.x], red[threadIdx.x + s]);
        __syncthreads();
    }
    const float scale = fmaxf(red[0] / WMAXQ, 1e-8f);
    if (threadIdx.x == 0) ws[o] = scale;

    for (int i = threadIdx.x; i < CCH * 9; i += blockDim.x) {
        int ci = i / 9, rs = i % 9;
        float k = fminf(fmaxf(rintf(wo[i] / scale), -WMAXQ), WMAXQ);
        size_t d = ((size_t)(((ci >> 4) * 9 + rs) * 128 + o) << 4) + (ci & 15);
        di[d] = __half_as_ushort(__float2half_rn(k));
    }
}

__global__ void prep_params(const float* g1, const float* b1, const float* m1, const float* v1,
                            const float* a1, const float* g2, const float* b2, const float* m2,
                            const float* v2, const float* a2, const float* a3) {
    const int c = threadIdx.x;
    if (c >= CCH) return;
    float sc1 = g1[c] / sqrtf(v1[c] + EPSBN);
    g_bns1[c] = sc1; g_bnb1[c] = b1[c] - m1[c] * sc1; g_a1p[c] = a1[c];
    g_s1[c] = a1[c] / QLEV; g_r1[c] = 1.0f / g_s1[c];
    float sc2 = g2[c] / sqrtf(v2[c] + EPSBN);
    g_bns2[c] = sc2; g_bnb2[c] = b2[c] - m2[c] * sc2; g_a2p[c] = a2[c];
    g_s2[c] = a2[c] / QLEV; g_r2[c] = 1.0f / g_s2[c];
    g_a3p[c] = a3[c]; g_s3[c] = a3[c] / QLEV; g_r3[c] = 1.0f / g_s3[c];
}

// ---------------- smem layout per buffer ----------------
// [0,3200) halo hi ; [3200,6400) halo lo ; [6400,24832) weights [rs9][co64][ci16]
#define WOFF   6400
#define BUFSZ  24832
#define SMTOT  (2 * BUFSZ)

// ---------------- fused conv stage: CTA 64px x 64co, 2 warps of 32px x 64co
// rs-loop software pipelined: fragments double-buffered across iterations.
template <int STAGE>
__global__ void __launch_bounds__(64, 4)
conv_mma(const float* __restrict__ x_res, float* __restrict__ out) {
    extern __shared__ char smem[];
    const uint32_t sb = smem_u32(smem);

    const int tid   = threadIdx.x;
    const int lane  = tid & 31;
    const int warpM = tid >> 5;

    const int w0  = (blockIdx.x >> 1) * 8;
    const int co0 = (blockIdx.x & 1) * 64;
    const int h0  = blockIdx.y * 8;
    const int n   = blockIdx.z;

    const unsigned short* __restrict__ srcHi = (STAGE == 1) ? g_xhi : g_a1hi;
    const unsigned short* __restrict__ srcLo = (STAGE == 1) ? g_xlo : g_a1lo;
    const unsigned short* __restrict__ wInt  = (STAGE == 1) ? g_w1i : g_w2i;
    const float* __restrict__ wScl           = (STAGE == 1) ? g_ws1 : g_ws2;

    // ---- ldmatrix lane addressing ----
    const int arow = lane & 15;
    const int akh  = (lane >> 4) * 16;
    const int bg   = lane >> 3;
    const int coL  = ((bg >> 1) << 3) + (lane & 7);
    const int bkh  = (bg & 1) * 16;
    uint32_t bAddrBase[4];
#pragma unroll
    for (int t = 0; t < 4; t++) {
        int co = t * 16 + coL;
        bAddrBase[t] = (uint32_t)WOFF + co * 32 + (uint32_t)(bkh ^ (((coL >> 2) & 1) * 16));
    }
    int phA[2], pwA[2];
#pragma unroll
    for (int m = 0; m < 2; m++) {
        int p = warpM * 32 + m * 16 + arow;
        phA[m] = p >> 3;
        pwA[m] = p & 7;
    }

    // ---- precomputed halo producer descriptors ----
    const unsigned short* hsrc[7];
    uint32_t hdoff[7];
    int hsz[7];
#pragma unroll
    for (int v = 0; v < 7; v++) {
        int e = tid + 64 * v;
        bool ok = e < 400;
        int pix = e >> 2, split = (e >> 1) & 1, half = e & 1;
        int hh = pix / 10, ww = pix % 10;
        int hg = h0 - 1 + hh, wg = w0 - 1 + ww;
        bool inb = ok & (hg >= 0) & (hg < HIMG) & (wg >= 0) & (wg < WIMG);
        size_t off = inb ? ((size_t)n * 401408 + (hg * 56 + wg) * 16 + half * 8) : 0;
        hsrc[v]  = (split ? srcLo : srcHi) + off;
        hdoff[v] = split * 3200 + (uint32_t)((pix * 32 + half * 16) ^ ((ww & 4) << 2));
        hsz[v]   = ok ? (inb ? 16 : 0) : -1;
    }

    auto issue_chunk = [&](int ck, int buf) {
        const uint32_t bufo = sb + buf * BUFSZ;
        const size_t cko = (size_t)ck * 50176;
#pragma unroll
        for (int v = 0; v < 7; v++)
            if (hsz[v] >= 0) cp16(bufo + hdoff[v], hsrc[v] + (hsz[v] ? cko : 0), hsz[v]);
        const unsigned short* wsrc = wInt + (size_t)ck * 18432 + co0 * 16;
#pragma unroll
        for (int j = 0; j < 18; j++) {
            int e2 = tid + 64 * j;
            int rs = e2 >> 7, u = e2 & 127;
            cp16(bufo + WOFF + (uint32_t)((e2 * 16) ^ ((e2 & 8) << 1)),
                 wsrc + rs * 2048 + u * 8, 16);
        }
        cp_commit();
    };

    float D[2][8][4];
#pragma unroll
    for (int m = 0; m < 2; m++)
#pragma unroll
        for (int f = 0; f < 8; f++)
#pragma unroll
            for (int j = 0; j < 4; j++) D[m][f][j] = 0.f;

    issue_chunk(0, 0);

    // pipelined fragment buffers
    uint32_t ah[2][2][4], al[2][2][4], bi[2][4][4];

    for (int ck = 0; ck < 8; ck++) {
        if (ck < 7) issue_chunk(ck + 1, (ck + 1) & 1);
        if (ck < 7) cp_wait<1>(); else cp_wait<0>();
        __syncthreads();

        const uint32_t sbuf = sb + (ck & 1) * BUFSZ;

        // prologue: load fragments for rs=0 into buffer 0
        {
            const int r0 = 0, s0 = 0;
#pragma unroll
            for (int m = 0; m < 2; m++) {
                const int wcol = pwA[m] + s0;
                uint32_t aaddr = sbuf + (uint32_t)(((phA[m] + r0) * 10 + wcol) * 32) +
                                 (uint32_t)(akh ^ (((wcol >> 2) & 1) * 16));
                ldsm4(ah[0][m], aaddr);
                ldsm4(al[0][m], aaddr + 3200);
            }
#pragma unroll
            for (int t = 0; t < 4; t++) ldsm4(bi[0][t], sbuf + bAddrBase[t]);
        }

#pragma unroll
        for (int rs = 0; rs < 9; rs++) {
            const int pb = rs & 1, nb = pb ^ 1;
            // prefetch fragments for rs+1 (before consuming rs)
            if (rs < 8) {
                const int rn = (rs + 1) / 3, sn = (rs + 1) % 3;
#pragma unroll
                for (int m = 0; m < 2; m++) {
                    const int wcol = pwA[m] + sn;
                    uint32_t aaddr = sbuf + (uint32_t)(((phA[m] + rn) * 10 + wcol) * 32) +
                                     (uint32_t)(akh ^ (((wcol >> 2) & 1) * 16));
                    ldsm4(ah[nb][m], aaddr);
                    ldsm4(al[nb][m], aaddr + 3200);
                }
                const uint32_t bbase = sbuf + (rs + 1) * 2048;
#pragma unroll
                for (int t = 0; t < 4; t++) ldsm4(bi[nb][t], bbase + bAddrBase[t]);
            }
            // scaled-B from fragments loaded one iteration ago (latency hidden)
            uint32_t bs[4][4];
#pragma unroll
            for (int t = 0; t < 4; t++)
#pragma unroll
                for (int q = 0; q < 4; q++) bs[t][q] = hscale11(bi[pb][t][q]);
            // 32 MMAs for iteration rs
#pragma unroll
            for (int m = 0; m < 2; m++)
#pragma unroll
                for (int t = 0; t < 4; t++)
#pragma unroll
                    for (int o = 0; o < 2; o++) {
                        const int nt = t * 2 + o;
                        mma16816(D[m][nt], ah[pb][m], bi[pb][t][o * 2], bi[pb][t][o * 2 + 1]);
                        mma16816(D[m][nt], al[pb][m], bs[t][o * 2], bs[t][o * 2 + 1]);
                    }
        }
        __syncthreads();
    }

    // ---------------- epilogue: BN+PACT into smem, coalesced writers ------
    float* qs = (float*)smem;
    const int qrow = lane >> 2;
    const int rr   = lane & 3;

#pragma unroll
    for (int m = 0; m < 2; m++)
#pragma unroll
        for (int nt = 0; nt < 8; nt++) {
            const int col = nt * 8;
#pragma unroll
            for (int j = 0; j < 4; j++) {
                const int cl_ = col + 2 * rr + (j & 1);
                const int co  = co0 + cl_;
                const int p   = warpM * 32 + m * 16 + qrow + (j >> 1) * 8;
                float d = D[m][nt][j] * wScl[co];
                float v, aa, ss, rr2;
                if (STAGE == 1) { v = d * g_bns1[co] + g_bnb1[co]; aa = g_a1p[co]; ss = g_s1[co]; rr2 = g_r1[co]; }
                else            { v = d * g_bns2[co] + g_bnb2[co]; aa = g_a2p[co]; ss = g_s2[co]; rr2 = g_r2[co]; }
                float cl2 = fminf(fmaxf(v, 0.f), aa);
                qs[p * 65 + cl_] = rintf(cl2 * rr2) * ss;
            }
        }
    __syncthreads();

    if (STAGE == 1) {
        const int px = tid;
        const int h = h0 + (px >> 3), w = w0 + (px & 7);
#pragma unroll
        for (int g = 0; g < 4; g++) {
            unsigned short vh[16], vl[16];
#pragma unroll
            for (int c = 0; c < 16; c++) {
                float q = qs[px * 65 + g * 16 + c];
                __half hh = __float2half_rn(q);
                vh[c] = __half_as_ushort(hh);
                vl[c] = __half_as_ushort(__float2half_rn((q - __half2float(hh)) * 2048.0f));
            }
            const int ck = (co0 >> 4) + g;
            size_t site = (((size_t)n * 8 + ck) * 56 + h) * 56 + w;
            unsigned short* dh = g_a1hi + site * 16;
            unsigned short* dl = g_a1lo + site * 16;
            ((uint4*)dh)[0] = ((uint4*)vh)[0]; ((uint4*)dh)[1] = ((uint4*)vh)[1];
            ((uint4*)dl)[0] = ((uint4*)vl)[0]; ((uint4*)dl)[1] = ((uint4*)vl)[1];
        }
    } else {
#pragma unroll
        for (int k = 0; k < 8; k++) {
            const int q   = tid + 64 * k;
            const int cl_ = q >> 3;
            const int hl  = q & 7;
            const int co  = co0 + cl_;
            const int h   = h0 + hl;
            const float s3  = g_s3[co];
            const float r3  = g_r3[co];
            const float a3v = g_a3p[co];
            const size_t base = (((size_t)n * 128 + co) * 56 + h) * 56 + w0;
            float4 x0 = *(const float4*)(x_res + base);
            float4 x1 = *(const float4*)(x_res + base + 4);
            float xv[8] = {x0.x, x0.y, x0.z, x0.w, x1.x, x1.y, x1.z, x1.w};
            float ov[8];
#pragma unroll
            for (int w = 0; w < 8; w++) {
                float qv = qs[(hl * 8 + w) * 65 + cl_];
                float y  = rintf(qv * r3) * s3 + rintf(xv[w] * r3) * s3;
                float yc = fminf(fmaxf(y, 0.f), a3v);
                ov[w] = rintf(yc * r3) * s3;
            }
            *(float4*)(out + base)     = make_float4(ov[0], ov[1], ov[2], ov[3]);
            *(float4*)(out + base + 4) = make_float4(ov[4], ov[5], ov[6], ov[7]);
        }
    }
}

// ---------------- launch ----------------
extern "C" void kernel_launch(void* const* d_in, const int* in_sizes, int n_in,
                              void* d_out, int out_size) {
    const float* x  = (const float*)d_in[0];
    const float* w1 = (const float*)d_in[1];
    const float* g1 = (const float*)d_in[2];
    const float* b1 = (const float*)d_in[3];
    const float* m1 = (const float*)d_in[4];
    const float* v1 = (const float*)d_in[5];
    const float* a1 = (const float*)d_in[6];
    const float* w2 = (const float*)d_in[7];
    const float* g2 = (const float*)d_in[8];
    const float* b2 = (const float*)d_in[9];
    const float* m2 = (const float*)d_in[10];
    const float* v2 = (const float*)d_in[11];
    const float* a2 = (const float*)d_in[12];
    const float* a3 = (const float*)d_in[13];
    float* out = (float*)d_out;

    cudaFuncSetAttribute(conv_mma<1>, cudaFuncAttributeMaxDynamicSharedMemorySize, SMTOT);
    cudaFuncSetAttribute(conv_mma<2>, cudaFuncAttributeMaxDynamicSharedMemorySize, SMTOT);

    presplit_x<<<3136, 256>>>(x);
    prep_weights<<<dim3(128, 2), 256>>>(w1, w2);
    prep_params<<<1, 128>>>(g1, b1, m1, v1, a1, g2, b2, m2, v2, a2, a3);

    dim3 grid(14, 7, 32);
    conv_mma<1><<<grid, 64, SMTOT>>>(nullptr, nullptr);
    conv_mma<2><<<grid, 64, SMTOT>>>(x, out);
}

// round 12
// speedup vs baseline: 1.0240x; 1.0240x over previous
#include <cuda_runtime.h>
#include <cuda_fp16.h>
#include <math.h>
#include <stdint.h>

#define CCH   128
#define HIMG  56
#define WIMG  56
#define NIMG  32
#define EPSBN 1e-5f
#define QLEV  255.0f
#define WMAXQ 127.0f

#define NPIX ((size_t)NIMG * CCH * HIMG * WIMG)

// ---------------- device scratch ----------------
__device__ unsigned short g_xhi[NPIX],  g_xlo[NPIX];
__device__ unsigned short g_a1hi[NPIX], g_a1lo[NPIX];
#define WELEMS (8 * 9 * 128 * 16)
__device__ unsigned short g_w1i[WELEMS], g_w2i[WELEMS];
__device__ float g_ws1[CCH], g_ws2[CCH];
__device__ float g_bns1[CCH], g_bnb1[CCH], g_a1p[CCH], g_s1[CCH], g_r1[CCH];
__device__ float g_bns2[CCH], g_bnb2[CCH], g_a2p[CCH], g_s2[CCH], g_r2[CCH];
__device__ float g_a3p[CCH], g_s3[CCH], g_r3[CCH];

// ---------------- PTX helpers ----------------
__device__ __forceinline__ uint32_t smem_u32(const void* p) {
    uint32_t a;
    asm("{ .reg .u64 t; cvta.to.shared.u64 t, %1; cvt.u32.u64 %0, t; }" : "=r"(a) : "l"(p));
    return a;
}

__device__ __forceinline__ void cp16(uint32_t dst, const void* src, int sz) {
    asm volatile("cp.async.cg.shared.global [%0], [%1], 16, %2;"
                 :: "r"(dst), "l"(__cvta_generic_to_global(src)), "r"(sz) : "memory");
}
__device__ __forceinline__ void cp_commit() {
    asm volatile("cp.async.commit_group;" ::: "memory");
}
template <int N> __device__ __forceinline__ void cp_wait() {
    asm volatile("cp.async.wait_group %0;" :: "n"(N) : "memory");
}

__device__ __forceinline__ void ldsm4(uint32_t r[4], uint32_t addr) {
    asm volatile("ldmatrix.sync.aligned.m8n8.x4.shared.b16 {%0,%1,%2,%3}, [%4];"
                 : "=r"(r[0]), "=r"(r[1]), "=r"(r[2]), "=r"(r[3]) : "r"(addr));
}

__device__ __forceinline__ void mma16816(float d[4], const uint32_t a[4],
                                         uint32_t b0, uint32_t b1) {
    asm volatile("mma.sync.aligned.m16n8k16.row.col.f32.f16.f16.f32 "
                 "{%0,%1,%2,%3}, {%4,%5,%6,%7}, {%8,%9}, {%0,%1,%2,%3};"
                 : "+f"(d[0]), "+f"(d[1]), "+f"(d[2]), "+f"(d[3])
                 : "r"(a[0]), "r"(a[1]), "r"(a[2]), "r"(a[3]), "r"(b0), "r"(b1));
}

// ---------------- prep kernels ----------------
__global__ void presplit_x(const float* __restrict__ x) {
    const size_t nsite = (size_t)NIMG * 8 * HIMG * WIMG;
    size_t i = (size_t)blockIdx.x * blockDim.x + threadIdx.x;
    if (i >= nsite) return;
    int w  = (int)(i % 56);
    int h  = (int)((i / 56) % 56);
    int ck = (int)((i / 3136) % 8);
    int n  = (int)(i / 25088);
    unsigned short hi[16], lo[16];
#pragma unroll
    for (int j = 0; j < 16; j++) {
        float v = x[((size_t)(n * 128 + ck * 16 + j)) * 3136 + h * 56 + w];
        __half hh = __float2half_rn(v);
        __half ll = __float2half_rn((v - __half2float(hh)) * 2048.0f);
        hi[j] = __half_as_ushort(hh);
        lo[j] = __half_as_ushort(ll);
    }
    uint4* dh = (uint4*)(g_xhi + i * 16);
    uint4* dl = (uint4*)(g_xlo + i * 16);
    dh[0] = ((uint4*)hi)[0]; dh[1] = ((uint4*)hi)[1];
    dl[0] = ((uint4*)lo)[0]; dl[1] = ((uint4*)lo)[1];
}

__global__ void prep_weights(const float* __restrict__ w1, const float* __restrict__ w2) {
    const int o = blockIdx.x;
    const float* w = (blockIdx.y == 0) ? w1 : w2;
    unsigned short* di = (blockIdx.y == 0) ? g_w1i : g_w2i;
    float* ws          = (blockIdx.y == 0) ? g_ws1 : g_ws2;
    const float* wo = w + (size_t)o * CCH * 9;

    float m = 0.f;
    for (int i = threadIdx.x; i < CCH * 9; i += blockDim.x)
        m = fmaxf(m, fabsf(wo[i]));
    __shared__ float red[256];
    red[threadIdx.x] = m;
    __syncthreads();
    for (int s = 128; s > 0; s >>= 1) {
        if (threadIdx.x < s) red[threadIdx.x] = fmaxf(red[threadIdx.x], red[threadIdx.x + s]);
        __syncthreads();
    }
    const float scale = fmaxf(red[0] / WMAXQ, 1e-8f);
    if (threadIdx.x == 0) ws[o] = scale;

    for (int i = threadIdx.x; i < CCH * 9; i += blockDim.x) {
        int ci = i / 9, rs = i % 9;
        float k = fminf(fmaxf(rintf(wo[i] / scale), -WMAXQ), WMAXQ);
        size_t d = ((size_t)(((ci >> 4) * 9 + rs) * 128 + o) << 4) + (ci & 15);
        di[d] = __half_as_ushort(__float2half_rn(k));
    }
}

__global__ void prep_params(const float* g1, const float* b1, const float* m1, const float* v1,
                            const float* a1, const float* g2, const float* b2, const float* m2,
                            const float* v2, const float* a2, const float* a3) {
    const int c = threadIdx.x;
    if (c >= CCH) return;
    float sc1 = g1[c] / sqrtf(v1[c] + EPSBN);
    g_bns1[c] = sc1; g_bnb1[c] = b1[c] - m1[c] * sc1; g_a1p[c] = a1[c];
    g_s1[c] = a1[c] / QLEV; g_r1[c] = 1.0f / g_s1[c];
    float sc2 = g2[c] / sqrtf(v2[c] + EPSBN);
    g_bns2[c] = sc2; g_bnb2[c] = b2[c] - m2[c] * sc2; g_a2p[c] = a2[c];
    g_s2[c] = a2[c] / QLEV; g_r2[c] = 1.0f / g_s2[c];
    g_a3p[c] = a3[c]; g_s3[c] = a3[c] / QLEV; g_r3[c] = 1.0f / g_s3[c];
}

// ---------------- smem layout per buffer ----------------
// [0,3200) halo hi ; [3200,6400) halo lo ; [6400,24832) weights [rs9][co64][ci16]
#define WOFF   6400
#define BUFSZ  24832
#define SMTOT  (2 * BUFSZ)

// ---------------- fused conv stage: CTA 64px x 64co, 2 warps of 32px x 64co
// dual accumulators (D0 hi-pass, D1 lo-pass): no in-loop B rescale.
template <int STAGE>
__global__ void __launch_bounds__(64, 4)
conv_mma(const float* __restrict__ x_res, float* __restrict__ out) {
    extern __shared__ char smem[];
    const uint32_t sb = smem_u32(smem);

    const int tid   = threadIdx.x;
    const int lane  = tid & 31;
    const int warpM = tid >> 5;

    const int w0  = (blockIdx.x >> 1) * 8;
    const int co0 = (blockIdx.x & 1) * 64;
    const int h0  = blockIdx.y * 8;
    const int n   = blockIdx.z;

    const unsigned short* __restrict__ srcHi = (STAGE == 1) ? g_xhi : g_a1hi;
    const unsigned short* __restrict__ srcLo = (STAGE == 1) ? g_xlo : g_a1lo;
    const unsigned short* __restrict__ wInt  = (STAGE == 1) ? g_w1i : g_w2i;
    const float* __restrict__ wScl           = (STAGE == 1) ? g_ws1 : g_ws2;

    // ---- ldmatrix lane addressing ----
    const int arow = lane & 15;
    const int akh  = (lane >> 4) * 16;
    const int bg   = lane >> 3;
    const int coL  = ((bg >> 1) << 3) + (lane & 7);
    const int bkh  = (bg & 1) * 16;
    uint32_t bAddrBase[4];
#pragma unroll
    for (int t = 0; t < 4; t++) {
        int co = t * 16 + coL;
        bAddrBase[t] = (uint32_t)WOFF + co * 32 + (uint32_t)(bkh ^ (((coL >> 2) & 1) * 16));
    }
    int phA[2], pwA[2];
#pragma unroll
    for (int m = 0; m < 2; m++) {
        int p = warpM * 32 + m * 16 + arow;
        phA[m] = p >> 3;
        pwA[m] = p & 7;
    }

    // ---- precomputed halo producer descriptors ----
    const unsigned short* hsrc[7];
    uint32_t hdoff[7];
    int hsz[7];
#pragma unroll
    for (int v = 0; v < 7; v++) {
        int e = tid + 64 * v;
        bool ok = e < 400;
        int pix = e >> 2, split = (e >> 1) & 1, half = e & 1;
        int hh = pix / 10, ww = pix % 10;
        int hg = h0 - 1 + hh, wg = w0 - 1 + ww;
        bool inb = ok & (hg >= 0) & (hg < HIMG) & (wg >= 0) & (wg < WIMG);
        size_t off = inb ? ((size_t)n * 401408 + (hg * 56 + wg) * 16 + half * 8) : 0;
        hsrc[v]  = (split ? srcLo : srcHi) + off;
        hdoff[v] = split * 3200 + (uint32_t)((pix * 32 + half * 16) ^ ((ww & 4) << 2));
        hsz[v]   = ok ? (inb ? 16 : 0) : -1;
    }

    auto issue_chunk = [&](int ck, int buf) {
        const uint32_t bufo = sb + buf * BUFSZ;
        const size_t cko = (size_t)ck * 50176;
#pragma unroll
        for (int v = 0; v < 7; v++)
            if (hsz[v] >= 0) cp16(bufo + hdoff[v], hsrc[v] + (hsz[v] ? cko : 0), hsz[v]);
        const unsigned short* wsrc = wInt + (size_t)ck * 18432 + co0 * 16;
#pragma unroll
        for (int j = 0; j < 18; j++) {
            int e2 = tid + 64 * j;
            int rs = e2 >> 7, u = e2 & 127;
            cp16(bufo + WOFF + (uint32_t)((e2 * 16) ^ ((e2 & 8) << 1)),
                 wsrc + rs * 2048 + u * 8, 16);
        }
        cp_commit();
    };

    float D0[2][8][4], D1[2][8][4];
#pragma unroll
    for (int m = 0; m < 2; m++)
#pragma unroll
        for (int f = 0; f < 8; f++)
#pragma unroll
            for (int j = 0; j < 4; j++) { D0[m][f][j] = 0.f; D1[m][f][j] = 0.f; }

    issue_chunk(0, 0);

    for (int ck = 0; ck < 8; ck++) {
        cp_wait<0>();
        __syncthreads();                       // all warps done with old buffer
        if (ck < 7) issue_chunk(ck + 1, (ck + 1) & 1);

        const uint32_t sbuf = sb + (ck & 1) * BUFSZ;
#pragma unroll
        for (int rs = 0; rs < 9; rs++) {
            const int r = rs / 3, s = rs % 3;
            uint32_t ah[2][4], al[2][4];
#pragma unroll
            for (int m = 0; m < 2; m++) {
                const int wcol = pwA[m] + s;
                uint32_t aaddr = sbuf + (uint32_t)(((phA[m] + r) * 10 + wcol) * 32) +
                                 (uint32_t)(akh ^ (((wcol >> 2) & 1) * 16));
                ldsm4(ah[m], aaddr);
                ldsm4(al[m], aaddr + 3200);
            }
            const uint32_t bbase = sbuf + rs * 2048;
            uint32_t bi[4][4];
#pragma unroll
            for (int t = 0; t < 4; t++) ldsm4(bi[t], bbase + bAddrBase[t]);
            // hi pass (16 independent accumulators)
#pragma unroll
            for (int m = 0; m < 2; m++)
#pragma unroll
                for (int t = 0; t < 4; t++)
#pragma unroll
                    for (int o = 0; o < 2; o++)
                        mma16816(D0[m][t * 2 + o], ah[m], bi[t][o * 2], bi[t][o * 2 + 1]);
            // lo pass
#pragma unroll
            for (int m = 0; m < 2; m++)
#pragma unroll
                for (int t = 0; t < 4; t++)
#pragma unroll
                    for (int o = 0; o < 2; o++)
                        mma16816(D1[m][t * 2 + o], al[m], bi[t][o * 2], bi[t][o * 2 + 1]);
        }
        __syncthreads();                       // reads of this buffer complete
    }

    // ---------------- epilogue: BN+PACT into smem, coalesced writers ------
    float* qs = (float*)smem;
    const int qrow = lane >> 2;
    const int rr   = lane & 3;
    const float inv2048 = 1.0f / 2048.0f;

#pragma unroll
    for (int m = 0; m < 2; m++)
#pragma unroll
        for (int nt = 0; nt < 8; nt++) {
            const int col = nt * 8;
#pragma unroll
            for (int j = 0; j < 4; j++) {
                const int cl_ = col + 2 * rr + (j & 1);
                const int co  = co0 + cl_;
                const int p   = warpM * 32 + m * 16 + qrow + (j >> 1) * 8;
                float d = (D0[m][nt][j] + D1[m][nt][j] * inv2048) * wScl[co];
                float v, aa, ss, rr2;
                if (STAGE == 1) { v = d * g_bns1[co] + g_bnb1[co]; aa = g_a1p[co]; ss = g_s1[co]; rr2 = g_r1[co]; }
                else            { v = d * g_bns2[co] + g_bnb2[co]; aa = g_a2p[co]; ss = g_s2[co]; rr2 = g_r2[co]; }
                float cl2 = fminf(fmaxf(v, 0.f), aa);
                qs[p * 65 + cl_] = rintf(cl2 * rr2) * ss;
            }
        }
    __syncthreads();

    if (STAGE == 1) {
        const int px = tid;
        const int h = h0 + (px >> 3), w = w0 + (px & 7);
#pragma unroll
        for (int g = 0; g < 4; g++) {
            unsigned short vh[16], vl[16];
#pragma unroll
            for (int c = 0; c < 16; c++) {
                float q = qs[px * 65 + g * 16 + c];
                __half hh = __float2half_rn(q);
                vh[c] = __half_as_ushort(hh);
                vl[c] = __half_as_ushort(__float2half_rn((q - __half2float(hh)) * 2048.0f));
            }
            const int ck = (co0 >> 4) + g;
            size_t site = (((size_t)n * 8 + ck) * 56 + h) * 56 + w;
            unsigned short* dh = g_a1hi + site * 16;
            unsigned short* dl = g_a1lo + site * 16;
            ((uint4*)dh)[0] = ((uint4*)vh)[0]; ((uint4*)dh)[1] = ((uint4*)vh)[1];
            ((uint4*)dl)[0] = ((uint4*)vl)[0]; ((uint4*)dl)[1] = ((uint4*)vl)[1];
        }
    } else {
#pragma unroll
        for (int k = 0; k < 8; k++) {
            const int q   = tid + 64 * k;
            const int cl_ = q >> 3;
            const int hl  = q & 7;
            const int co  = co0 + cl_;
            const int h   = h0 + hl;
            const float s3  = g_s3[co];
            const float r3  = g_r3[co];
            const float a3v = g_a3p[co];
            const size_t base = (((size_t)n * 128 + co) * 56 + h) * 56 + w0;
            float4 x0 = *(const float4*)(x_res + base);
            float4 x1 = *(const float4*)(x_res + base + 4);
            float xv[8] = {x0.x, x0.y, x0.z, x0.w, x1.x, x1.y, x1.z, x1.w};
            float ov[8];
#pragma unroll
            for (int w = 0; w < 8; w++) {
                float qv = qs[(hl * 8 + w) * 65 + cl_];
                float y  = rintf(qv * r3) * s3 + rintf(xv[w] * r3) * s3;
                float yc = fminf(fmaxf(y, 0.f), a3v);
                ov[w] = rintf(yc * r3) * s3;
            }
            *(float4*)(out + base)     = make_float4(ov[0], ov[1], ov[2], ov[3]);
            *(float4*)(out + base + 4) = make_float4(ov[4], ov[5], ov[6], ov[7]);
        }
    }
}

// ---------------- launch ----------------
extern "C" void kernel_launch(void* const* d_in, const int* in_sizes, int n_in,
                              void* d_out, int out_size) {
    const float* x  = (const float*)d_in[0];
    const float* w1 = (const float*)d_in[1];
    const float* g1 = (const float*)d_in[2];
    const float* b1 = (const float*)d_in[3];
    const float* m1 = (const float*)d_in[4];
    const float* v1 = (const float*)d_in[5];
    const float* a1 = (const float*)d_in[6];
    const float* w2 = (const float*)d_in[7];
    const float* g2 = (const float*)d_in[8];
    const float* b2 = (const float*)d_in[9];
    const float* m2 = (const float*)d_in[10];
    const float* v2 = (const float*)d_in[11];
    const float* a2 = (const float*)d_in[12];
    const float* a3 = (const float*)d_in[13];
    float* out = (float*)d_out;

    cudaFuncSetAttribute(conv_mma<1>, cudaFuncAttributeMaxDynamicSharedMemorySize, SMTOT);
    cudaFuncSetAttribute(conv_mma<2>, cudaFuncAttributeMaxDynamicSharedMemorySize, SMTOT);

    presplit_x<<<3136, 256>>>(x);
    prep_weights<<<dim3(128, 2), 256>>>(w1, w2);
    prep_params<<<1, 128>>>(g1, b1, m1, v1, a1, g2, b2, m2, v2, a2, a3);

    dim3 grid(14, 7, 32);
    conv_mma<1><<<grid, 64, SMTOT>>>(nullptr, nullptr);
    conv_mma<2><<<grid, 64, SMTOT>>>(x, out);
}